// round 8
// baseline (speedup 1.0000x reference)
#include <cuda_runtime.h>

// Problem constants
#define Bn 4
#define Tn 2048
#define Dn 1024
#define Hn 16
#define Kd 64
#define HK 1024

// q pre-scale: (1/sqrt(64)) * log2(e)  -> softmax done in base-2 domain
#define QSC 0.18033688011112042f

// ---- tf32 scratch (bit patterns stored as unsigned) ----
__device__ unsigned g_xt[Bn * Tn * Dn];          // X tf32 [8192][1024]
__device__ unsigned g_wall[3072 * 1024];         // gathered W^T tf32 [n][d]
__device__ unsigned g_wot[1024 * 1024];          // Wo tf32 [n][k]
__device__ unsigned g_q[Bn * Hn * Tn * Kd];      // tf32, pre-scaled [bh][t][d]
__device__ unsigned g_k[Bn * Hn * Tn * Kd];      // tf32 [bh][t][d]
__device__ unsigned g_vt[Bn * Hn * Kd * Tn];     // tf32 [bh][d][t]
__device__ unsigned g_ao[Bn * Tn * HK];          // tf32 [b*t][h*64+c]

__device__ __forceinline__ unsigned f2tf(float x) {
    unsigned r; asm("cvt.rna.tf32.f32 %0, %1;" : "=r"(r) : "f"(x)); return r;
}
__device__ __forceinline__ void mma8(float* c, const unsigned* a, unsigned b0, unsigned b1) {
    asm("mma.sync.aligned.m16n8k8.row.col.f32.tf32.tf32.f32 "
        "{%0,%1,%2,%3}, {%4,%5,%6,%7}, {%8,%9}, {%0,%1,%2,%3};"
        : "+f"(c[0]), "+f"(c[1]), "+f"(c[2]), "+f"(c[3])
        : "r"(a[0]), "r"(a[1]), "r"(a[2]), "r"(a[3]), "r"(b0), "r"(b1));
}
__device__ __forceinline__ void ldsm4(unsigned r[4], unsigned addr) {
    asm volatile("ldmatrix.sync.aligned.m8n8.x4.shared.b16 {%0,%1,%2,%3}, [%4];"
                 : "=r"(r[0]), "=r"(r[1]), "=r"(r[2]), "=r"(r[3]) : "r"(addr));
}
__device__ __forceinline__ void cpa16(unsigned d, const void* s) {
    asm volatile("cp.async.ca.shared.global [%0], [%1], 16;" :: "r"(d), "l"(s));
}
#define CP_COMMIT asm volatile("cp.async.commit_group;")
#define CP_WAIT0  asm volatile("cp.async.wait_group 0;")
#define CP_WAIT1  asm volatile("cp.async.wait_group 1;")
__device__ __forceinline__ unsigned cvta_s(const void* p) {
    return (unsigned)__cvta_generic_to_shared(p);
}

// ---------------------------------------------------------------------------
// Prepass A: elementwise fp32->tf32 for X and Wo
// ---------------------------------------------------------------------------
__global__ __launch_bounds__(256) void conv_kernel(const float4* __restrict__ X,
                                                   const float4* __restrict__ Wo)
{
    int idx = blockIdx.x * 256 + threadIdx.x;
    float4 v = X[idx];
    uint4 o;
    o.x = f2tf(v.x); o.y = f2tf(v.y); o.z = f2tf(v.z); o.w = f2tf(v.w);
    *(uint4*)&g_xt[idx * 4] = o;
    if (idx < 262144) {
        float4 w = Wo[idx];
        uint4 ow;
        ow.x = f2tf(w.x); ow.y = f2tf(w.y); ow.z = f2tf(w.z); ow.w = f2tf(w.w);
        *(uint4*)&g_wot[idx * 4] = ow;
    }
}

// ---------------------------------------------------------------------------
// Prepass B: gather+transpose W{q,k,v}[h] (D x 64, k-major) -> g_wall[n][d]
// ---------------------------------------------------------------------------
__global__ __launch_bounds__(256) void gather_w(const float* __restrict__ Wq,
                                                const float* __restrict__ Wk,
                                                const float* __restrict__ Wv)
{
    __shared__ unsigned t[32][65];
    const int d0 = blockIdx.x * 32;
    const int wh = blockIdx.y;
    const int which = wh >> 4, h = wh & 15;
    const float* W = ((which == 0) ? Wq : (which == 1) ? Wk : Wv) + (size_t)h * Dn * Kd;
    const int tid = threadIdx.x;
#pragma unroll
    for (int i = 0; i < 8; i++) {
        int idx = tid + 256 * i;
        int dr = idx >> 6, c = idx & 63;
        t[dr][c] = f2tf(W[(size_t)(d0 + dr) * 64 + c]);
    }
    __syncthreads();
#pragma unroll
    for (int i = 0; i < 8; i++) {
        int idx = tid + 256 * i;
        int row = idx >> 5, dd = idx & 31;
        g_wall[(size_t)((which << 10) + (h << 6) + row) * 1024 + d0 + dd] = t[dd][row];
    }
}

// ---------------------------------------------------------------------------
// GEMM mainloop: block 128x128, 128 threads = 4 warps (2m x 2n), warp 64x64.
// K in 32-chunks, 3-stage cp.async ring (prefetch distance 2), ldmatrix,
// XOR-swizzled 32-word rows.  Per k8-step: 8 LDSM feed 32 HMMA.
// ---------------------------------------------------------------------------
#define GEMM_MAIN(Aptr, Bptr)                                                    \
    const int tid = threadIdx.x;                                                 \
    const int w = tid >> 5, lane = tid & 31;                                     \
    const int g = lane >> 2, tig = lane & 3;                                     \
    const int wm = w >> 1, wn = w & 1;                                           \
    const int rl = lane & 7, sub = lane >> 3;                                    \
    const int shA = sub >> 1, shB = sub & 1;                                     \
    extern __shared__ unsigned sm[];                                             \
    const unsigned sA = cvta_s(sm);                                              \
    /* fill mapping: 16 cpa16/thread/stage; row=(tid>>3)+16i, chunk c=tid&7 */   \
    const int r0f = tid >> 3, cf = tid & 7;                                      \
    const unsigned fdst = (unsigned)((r0f * 32 + ((cf ^ (r0f & 7)) << 2)) << 2); \
    /* ldsm lane constants: A 4 x 16-row groups, B 4 x 16-col groups */          \
    int wA[4], xA[4], wB[4], xB[4];                                              \
    _Pragma("unroll") for (int mi = 0; mi < 4; mi++) {                           \
        int ra = wm * 64 + mi * 16 + ((sub & 1) << 3) + rl;                      \
        wA[mi] = ra * 32; xA[mi] = ra & 7; }                                     \
    _Pragma("unroll") for (int nj = 0; nj < 4; nj++) {                           \
        int rb = wn * 64 + nj * 16 + ((sub >> 1) << 3) + rl;                     \
        wB[nj] = rb * 32; xB[nj] = rb & 7; }                                     \
    float acc[4][8][4];                                                          \
    _Pragma("unroll") for (int mi = 0; mi < 4; mi++)                             \
    _Pragma("unroll") for (int ni = 0; ni < 8; ni++)                             \
    _Pragma("unroll") for (int q = 0; q < 4; q++) acc[mi][ni][q] = 0.f;          \
    /* prefetch stages 0,1 */                                                    \
    _Pragma("unroll") for (int st = 0; st < 2; st++) {                           \
        unsigned sb = sA + st * 32768;                                           \
        int kk = st * 32;                                                        \
        _Pragma("unroll") for (int i = 0; i < 8; i++) {                          \
            cpa16(sb + fdst + i * 2048,                                          \
                  Aptr + (size_t)(r0f + 16 * i) * 1024 + kk + cf * 4);           \
            cpa16(sb + 16384 + fdst + i * 2048,                                  \
                  Bptr + (size_t)(r0f + 16 * i) * 1024 + kk + cf * 4); }         \
        CP_COMMIT;                                                               \
    }                                                                            \
    for (int it = 0; it < 32; it++) {                                            \
        if (it + 1 < 32) { CP_WAIT1; } else { CP_WAIT0; }                        \
        __syncthreads();                                                         \
        if (it + 2 < 32) {                                                       \
            int st = it + 2;                                                     \
            unsigned sb = sA + (st - (st / 3) * 3) * 32768;                      \
            int kk = st * 32;                                                    \
            _Pragma("unroll") for (int i = 0; i < 8; i++) {                      \
                cpa16(sb + fdst + i * 2048,                                      \
                      Aptr + (size_t)(r0f + 16 * i) * 1024 + kk + cf * 4);       \
                cpa16(sb + 16384 + fdst + i * 2048,                              \
                      Bptr + (size_t)(r0f + 16 * i) * 1024 + kk + cf * 4); }     \
            CP_COMMIT;                                                           \
        }                                                                        \
        const unsigned sAb = sA + (it - (it / 3) * 3) * 32768;                   \
        const unsigned sBb = sAb + 16384;                                        \
        _Pragma("unroll") for (int ks = 0; ks < 4; ks++) {                       \
            unsigned af[4][4], bq[4][4];                                         \
            _Pragma("unroll") for (int mi = 0; mi < 4; mi++)                     \
                ldsm4(af[mi], sAb + ((wA[mi] + (((2 * ks + shA) ^ xA[mi]) << 2)) << 2)); \
            _Pragma("unroll") for (int nj = 0; nj < 4; nj++)                     \
                ldsm4(bq[nj], sBb + ((wB[nj] + (((2 * ks + shB) ^ xB[nj]) << 2)) << 2)); \
            _Pragma("unroll") for (int mi = 0; mi < 4; mi++)                     \
            _Pragma("unroll") for (int ni = 0; ni < 8; ni++)                     \
                mma8(acc[mi][ni], af[mi], bq[ni >> 1][(ni & 1) * 2],             \
                     bq[ni >> 1][(ni & 1) * 2 + 1]);                             \
        }                                                                        \
    }

#define GEMM_SMEM (3 * 32768)

// ---------------------------------------------------------------------------
// Kernel 1: fused QKV GEMM; q pre-scaled by QSC (1/sqrt(K) * log2e)
// ---------------------------------------------------------------------------
__global__ __launch_bounds__(128, 2) void qkv_mma()
{
    const int mblk = blockIdx.x;          // 0..63
    const int nblk = blockIdx.y;          // 0..23
    const unsigned* Ag = g_xt + (size_t)mblk * 128 * Dn;
    const unsigned* Bg = g_wall + (size_t)nblk * 128 * 1024;

    GEMM_MAIN(Ag, Bg)

    const int which = nblk >> 3;
#pragma unroll
    for (int mi = 0; mi < 4; mi++) {
        int m = mblk * 128 + wm * 64 + mi * 16 + g;
        int b = m >> 11, t = m & 2047;
#pragma unroll
        for (int ni = 0; ni < 8; ni++) {
            int nl = nblk * 128 + wn * 64 + ni * 8 + 2 * tig;
            int hh = (nl >> 6) & 15, kcol = nl & 63;
            float c0 = acc[mi][ni][0], c1 = acc[mi][ni][1];
            float c2 = acc[mi][ni][2], c3 = acc[mi][ni][3];
            if (which == 0) {
                unsigned* p = g_q + ((size_t)(b * 16 + hh) * Tn + t) * 64 + kcol;
                *(uint2*)p = make_uint2(f2tf(c0 * QSC), f2tf(c1 * QSC));
                *(uint2*)(p + 8 * 64) = make_uint2(f2tf(c2 * QSC), f2tf(c3 * QSC));
            } else if (which == 1) {
                unsigned* p = g_k + ((size_t)(b * 16 + hh) * Tn + t) * 64 + kcol;
                *(uint2*)p = make_uint2(f2tf(c0), f2tf(c1));
                *(uint2*)(p + 8 * 64) = make_uint2(f2tf(c2), f2tf(c3));
            } else {
                unsigned* p = g_vt + ((size_t)(b * 16 + hh) * 64 + kcol) * Tn + t;
                p[0] = f2tf(c0); p[Tn] = f2tf(c1);
                p[8] = f2tf(c2); p[Tn + 8] = f2tf(c3);
            }
        }
    }
}

// ---------------------------------------------------------------------------
// Kernel 3: output projection
// ---------------------------------------------------------------------------
__global__ __launch_bounds__(128, 2) void proj_mma(const float* __restrict__ bo,
                                                   float* __restrict__ Y)
{
    const int mblk = blockIdx.x;  // 0..63
    const int nblk = blockIdx.y;  // 0..7
    const unsigned* Ag = g_ao + (size_t)mblk * 128 * HK;
    const unsigned* Bg = g_wot + (size_t)nblk * 128 * 1024;

    GEMM_MAIN(Ag, Bg)

#pragma unroll
    for (int mi = 0; mi < 4; mi++) {
        int m = mblk * 128 + wm * 64 + mi * 16 + g;
#pragma unroll
        for (int ni = 0; ni < 8; ni++) {
            int n = nblk * 128 + wn * 64 + ni * 8 + 2 * tig;
            float2 bb = *(const float2*)(bo + n);
            *(float2*)(Y + (size_t)m * HK + n) =
                make_float2(acc[mi][ni][0] + bb.x, acc[mi][ni][1] + bb.y);
            *(float2*)(Y + (size_t)(m + 8) * HK + n) =
                make_float2(acc[mi][ni][2] + bb.x, acc[mi][ni][3] + bb.y);
        }
    }
}

// ---------------------------------------------------------------------------
// Kernel 2: causal flash attention (R5, known good). 128 threads = 4 warps,
// warp owns 32 q-rows.  smem: Q/P 128x64, K 2x64x64, V 2x64x64.  96 KB.
// ---------------------------------------------------------------------------
__global__ __launch_bounds__(128, 2) void attn_kernel()
{
    extern __shared__ unsigned sm[];
    const unsigned sQ = cvta_s(sm);
    const unsigned sK = sQ + 8192 * 4;
    const unsigned sV = sK + 2 * 4096 * 4;

    const int qb = (int)gridDim.x - 1 - (int)blockIdx.x;  // big tiles first
    const int bh = blockIdx.y;
    const int b = bh >> 4, h = bh & 15;

    const int tid = threadIdx.x;
    const int w = tid >> 5, lane = tid & 31;
    const int g = lane >> 2, tig = lane & 3;
    const int rl = lane & 7, sub = lane >> 3;
    const int shq = sub >> 1, shb = sub & 1;

    const unsigned* Qg = g_q + ((size_t)bh * Tn + (size_t)qb * 128) * 64;
    const unsigned* Kg = g_k + (size_t)bh * Tn * 64;
    const unsigned* Vt = g_vt + (size_t)bh * 64 * Tn;

    const int frow = tid >> 4, fc = tid & 15;
    const unsigned foff = ((frow * 64 + ((fc >> 3) << 5) +
                            (((fc & 7) ^ (frow & 7)) << 2)) << 2);

#pragma unroll
    for (int i = 0; i < 16; i++)
        cpa16(sQ + foff + i * 2048, Qg + (size_t)(frow + 8 * i) * 64 + fc * 4);
#pragma unroll
    for (int i = 0; i < 8; i++) {
        cpa16(sK + foff + i * 2048, Kg + (size_t)(frow + 8 * i) * 64 + fc * 4);
        cpa16(sV + foff + i * 2048, Vt + (size_t)(frow + 8 * i) * Tn + fc * 4);
    }
    CP_COMMIT;
    CP_WAIT0;
    __syncthreads();

    unsigned qf[8][2][4];
    int wqm[2], xqm[2];
#pragma unroll
    for (int mi = 0; mi < 2; mi++) {
        int rowQ = w * 32 + mi * 16 + ((sub & 1) << 3) + rl;
        wqm[mi] = rowQ * 64; xqm[mi] = rowQ & 7;
#pragma unroll
        for (int ks = 0; ks < 8; ks++)
            ldsm4(qf[ks][mi], sQ + ((wqm[mi] + ((ks & 4) << 3) +
                  ((((2 * ks) & 7) + shq ^ xqm[mi]) << 2)) << 2));
    }

    int rowB0 = ((sub >> 1) << 3) + rl;
    int wKB[4], xKB[4];
#pragma unroll
    for (int nj = 0; nj < 4; nj++) {
        int rb = rowB0 + nj * 16; wKB[nj] = rb * 64; xKB[nj] = rb & 7;
    }

    float mrow[4], lrow[4];
    float o[2][8][4];
#pragma unroll
    for (int q = 0; q < 4; q++) { mrow[q] = -1e30f; lrow[q] = 0.f; }
#pragma unroll
    for (int mi = 0; mi < 2; mi++)
#pragma unroll
        for (int ni = 0; ni < 8; ni++)
#pragma unroll
            for (int q = 0; q < 4; q++) o[mi][ni][q] = 0.f;

    const int kbmax = 2 * qb + 1;

    for (int kb = 0; kb <= kbmax; kb++) {
        const int buf = kb & 1;
        if (kb) { CP_WAIT0; __syncthreads(); }
        if (kb < kbmax) {
            unsigned off = (buf ^ 1) * 16384;
            int s0g = (kb + 1) * 64;
#pragma unroll
            for (int i = 0; i < 8; i++) {
                cpa16(sK + off + foff + i * 2048,
                      Kg + (size_t)(s0g + frow + 8 * i) * 64 + fc * 4);
                cpa16(sV + off + foff + i * 2048,
                      Vt + (size_t)(frow + 8 * i) * Tn + s0g + fc * 4);
            }
            CP_COMMIT;
        }
        const unsigned stK = sK + buf * 16384;
        const unsigned stV = sV + buf * 16384;

        float s[2][8][4];
#pragma unroll
        for (int mi = 0; mi < 2; mi++)
#pragma unroll
            for (int ni = 0; ni < 8; ni++)
#pragma unroll
                for (int q = 0; q < 4; q++) s[mi][ni][q] = 0.f;
#pragma unroll
        for (int ks = 0; ks < 8; ks++) {
            unsigned bq[4][4];
#pragma unroll
            for (int nj = 0; nj < 4; nj++)
                ldsm4(bq[nj], stK + ((wKB[nj] + ((ks & 4) << 3) +
                      ((((2 * ks) & 7) + shb ^ xKB[nj]) << 2)) << 2));
#pragma unroll
            for (int ni = 0; ni < 8; ni++) {
                unsigned b0 = bq[ni >> 1][(ni & 1) * 2];
                unsigned b1 = bq[ni >> 1][(ni & 1) * 2 + 1];
                mma8(s[0][ni], qf[ks][0], b0, b1);
                mma8(s[1][ni], qf[ks][1], b0, b1);
            }
        }

        if (kb >= 2 * qb) {
#pragma unroll
            for (int mi = 0; mi < 2; mi++) {
                int grow0 = qb * 128 + w * 32 + mi * 16 + g;
#pragma unroll
                for (int ni = 0; ni < 8; ni++) {
                    int col = kb * 64 + ni * 8 + 2 * tig;
                    if (col > grow0)         s[mi][ni][0] = -1e30f;
                    if (col + 1 > grow0)     s[mi][ni][1] = -1e30f;
                    if (col > grow0 + 8)     s[mi][ni][2] = -1e30f;
                    if (col + 1 > grow0 + 8) s[mi][ni][3] = -1e30f;
                }
            }
        }

#pragma unroll
        for (int mi = 0; mi < 2; mi++) {
            float x0 = -1e30f, x1 = -1e30f;
#pragma unroll
            for (int ni = 0; ni < 8; ni++) {
                x0 = fmaxf(x0, fmaxf(s[mi][ni][0], s[mi][ni][1]));
                x1 = fmaxf(x1, fmaxf(s[mi][ni][2], s[mi][ni][3]));
            }
#pragma unroll
            for (int off = 1; off < 4; off <<= 1) {
                x0 = fmaxf(x0, __shfl_xor_sync(0xffffffffu, x0, off));
                x1 = fmaxf(x1, __shfl_xor_sync(0xffffffffu, x1, off));
            }
            float m0 = mrow[mi * 2], m1 = mrow[mi * 2 + 1];
            float mn0 = fmaxf(m0, x0), mn1 = fmaxf(m1, x1);
            float corr0 = exp2f(m0 - mn0), corr1 = exp2f(m1 - mn1);
            mrow[mi * 2] = mn0; mrow[mi * 2 + 1] = mn1;

            int rr0 = w * 32 + mi * 16 + g;
            int rr1 = rr0 + 8;
            float rs0 = 0.f, rs1 = 0.f;
#pragma unroll
            for (int ni = 0; ni < 8; ni++) {
                unsigned t0 = f2tf(exp2f(s[mi][ni][0] - mn0));
                unsigned t1 = f2tf(exp2f(s[mi][ni][1] - mn0));
                unsigned t2 = f2tf(exp2f(s[mi][ni][2] - mn1));
                unsigned t3 = f2tf(exp2f(s[mi][ni][3] - mn1));
                rs0 += __uint_as_float(t0) + __uint_as_float(t1);
                rs1 += __uint_as_float(t2) + __uint_as_float(t3);
                int col = ni * 8 + 2 * tig;
                unsigned w0 = (rr0 * 64 + (col & 32) +
                               ((((col >> 2) & 7) ^ (rr0 & 7)) << 2) + (col & 3)) << 2;
                unsigned w1 = (rr1 * 64 + (col & 32) +
                               ((((col >> 2) & 7) ^ (rr1 & 7)) << 2) + (col & 3)) << 2;
                *(uint2*)((char*)sm + w0) = make_uint2(t0, t1);
                *(uint2*)((char*)sm + w1) = make_uint2(t2, t3);
            }
#pragma unroll
            for (int off = 1; off < 4; off <<= 1) {
                rs0 += __shfl_xor_sync(0xffffffffu, rs0, off);
                rs1 += __shfl_xor_sync(0xffffffffu, rs1, off);
            }
            lrow[mi * 2] = lrow[mi * 2] * corr0 + rs0;
            lrow[mi * 2 + 1] = lrow[mi * 2 + 1] * corr1 + rs1;
#pragma unroll
            for (int ni = 0; ni < 8; ni++) {
                o[mi][ni][0] *= corr0; o[mi][ni][1] *= corr0;
                o[mi][ni][2] *= corr1; o[mi][ni][3] *= corr1;
            }
        }
        __syncwarp();

#pragma unroll
        for (int ss = 0; ss < 8; ss++) {
            unsigned pa[2][4];
#pragma unroll
            for (int mi = 0; mi < 2; mi++)
                ldsm4(pa[mi], sQ + ((wqm[mi] + ((ss & 4) << 3) +
                      ((((2 * ss) & 7) + shq ^ xqm[mi]) << 2)) << 2));
            unsigned bq[4][4];
#pragma unroll
            for (int nj = 0; nj < 4; nj++)
                ldsm4(bq[nj], stV + ((wKB[nj] + ((ss & 4) << 3) +
                      ((((2 * ss) & 7) + shb ^ xKB[nj]) << 2)) << 2));
#pragma unroll
            for (int ni = 0; ni < 8; ni++) {
                unsigned b0 = bq[ni >> 1][(ni & 1) * 2];
                unsigned b1 = bq[ni >> 1][(ni & 1) * 2 + 1];
                mma8(o[0][ni], pa[0], b0, b1);
                mma8(o[1][ni], pa[1], b0, b1);
            }
        }
        __syncwarp();
    }

#pragma unroll
    for (int mi = 0; mi < 2; mi++) {
        float inv0 = 1.0f / lrow[mi * 2], inv1 = 1.0f / lrow[mi * 2 + 1];
        int rr = qb * 128 + w * 32 + mi * 16 + g;
        unsigned* Og = g_ao + ((size_t)b * Tn + rr) * HK + (size_t)h * Kd;
#pragma unroll
        for (int ni = 0; ni < 8; ni++) {
            int col = ni * 8 + 2 * tig;
            *(uint2*)(Og + col) =
                make_uint2(f2tf(o[mi][ni][0] * inv0), f2tf(o[mi][ni][1] * inv0));
            *(uint2*)(Og + 8 * HK + col) =
                make_uint2(f2tf(o[mi][ni][2] * inv1), f2tf(o[mi][ni][3] * inv1));
        }
    }
}

// ---------------------------------------------------------------------------
extern "C" void kernel_launch(void* const* d_in, const int* in_sizes, int n_in,
                              void* d_out, int out_size)
{
    (void)in_sizes; (void)n_in; (void)out_size;
    const float* X  = (const float*)d_in[0];
    const float* Wq = (const float*)d_in[1];
    const float* Wk = (const float*)d_in[2];
    const float* Wv = (const float*)d_in[3];
    const float* Wo = (const float*)d_in[4];
    const float* bo = (const float*)d_in[5];
    float* Y = (float*)d_out;

    const int attn_smem = (8192 + 2 * 4096 + 2 * 4096) * 4;  // 96 KB
    cudaFuncSetAttribute(attn_kernel, cudaFuncAttributeMaxDynamicSharedMemorySize, attn_smem);
    cudaFuncSetAttribute(qkv_mma,  cudaFuncAttributeMaxDynamicSharedMemorySize, GEMM_SMEM);
    cudaFuncSetAttribute(proj_mma, cudaFuncAttributeMaxDynamicSharedMemorySize, GEMM_SMEM);

    conv_kernel<<<8192, 256>>>((const float4*)X, (const float4*)Wo);
    gather_w<<<dim3(32, 48), 256>>>(Wq, Wk, Wv);
    qkv_mma<<<dim3(64, 24), 128, GEMM_SMEM>>>();
    attn_kernel<<<dim3(Tn / 128, Bn * Hn), 128, attn_smem>>>();
    proj_mma<<<dim3(64, 8), 128, GEMM_SMEM>>>(bo, Y);
}

// round 11
// speedup vs baseline: 1.0267x; 1.0267x over previous
#include <cuda_runtime.h>

// Problem constants
#define Bn 4
#define Tn 2048
#define Dn 1024
#define Hn 16
#define Kd 64
#define HK 1024

// q pre-scale: (1/sqrt(64)) * log2(e)  -> softmax done in base-2 domain
#define QSC 0.18033688011112042f

// ---- tf32 scratch (bit patterns stored as unsigned) ----
__device__ unsigned g_xt[Bn * Tn * Dn];          // X tf32 [8192][1024]
__device__ unsigned g_wall[3072 * 1024];         // gathered W^T tf32 [n][d]
__device__ unsigned g_wot[1024 * 1024];          // Wo tf32 [n][k]
__device__ unsigned g_q[Bn * Hn * Tn * Kd];      // tf32, pre-scaled [bh][t][d]
__device__ unsigned g_k[Bn * Hn * Tn * Kd];      // tf32 [bh][t][d]
__device__ unsigned g_vt[Bn * Hn * Kd * Tn];     // tf32 [bh][d][t]
__device__ unsigned g_ao[Bn * Tn * HK];          // tf32 [b*t][h*64+c]

__device__ __forceinline__ unsigned f2tf(float x) {
    unsigned r; asm("cvt.rna.tf32.f32 %0, %1;" : "=r"(r) : "f"(x)); return r;
}
__device__ __forceinline__ void mma8(float* c, const unsigned* a, unsigned b0, unsigned b1) {
    asm("mma.sync.aligned.m16n8k8.row.col.f32.tf32.tf32.f32 "
        "{%0,%1,%2,%3}, {%4,%5,%6,%7}, {%8,%9}, {%0,%1,%2,%3};"
        : "+f"(c[0]), "+f"(c[1]), "+f"(c[2]), "+f"(c[3])
        : "r"(a[0]), "r"(a[1]), "r"(a[2]), "r"(a[3]), "r"(b0), "r"(b1));
}
__device__ __forceinline__ void ldsm4(unsigned r[4], unsigned addr) {
    asm volatile("ldmatrix.sync.aligned.m8n8.x4.shared.b16 {%0,%1,%2,%3}, [%4];"
                 : "=r"(r[0]), "=r"(r[1]), "=r"(r[2]), "=r"(r[3]) : "r"(addr));
}
__device__ __forceinline__ void cpa16(unsigned d, const void* s) {
    asm volatile("cp.async.ca.shared.global [%0], [%1], 16;" :: "r"(d), "l"(s));
}
#define CP_COMMIT asm volatile("cp.async.commit_group;")
#define CP_WAIT0  asm volatile("cp.async.wait_group 0;")
__device__ __forceinline__ unsigned cvta_s(const void* p) {
    return (unsigned)__cvta_generic_to_shared(p);
}

// ---------------------------------------------------------------------------
// Prepass A: elementwise fp32->tf32 for X and Wo
// ---------------------------------------------------------------------------
__global__ __launch_bounds__(256) void conv_kernel(const float4* __restrict__ X,
                                                   const float4* __restrict__ Wo)
{
    int idx = blockIdx.x * 256 + threadIdx.x;
    float4 v = X[idx];
    uint4 o;
    o.x = f2tf(v.x); o.y = f2tf(v.y); o.z = f2tf(v.z); o.w = f2tf(v.w);
    *(uint4*)&g_xt[idx * 4] = o;
    if (idx < 262144) {
        float4 w = Wo[idx];
        uint4 ow;
        ow.x = f2tf(w.x); ow.y = f2tf(w.y); ow.z = f2tf(w.z); ow.w = f2tf(w.w);
        *(uint4*)&g_wot[idx * 4] = ow;
    }
}

// ---------------------------------------------------------------------------
// Prepass B: gather+transpose W{q,k,v}[h] (D x 64, k-major) -> g_wall[n][d]
// ---------------------------------------------------------------------------
__global__ __launch_bounds__(256) void gather_w(const float* __restrict__ Wq,
                                                const float* __restrict__ Wk,
                                                const float* __restrict__ Wv)
{
    __shared__ unsigned t[32][65];
    const int d0 = blockIdx.x * 32;
    const int wh = blockIdx.y;
    const int which = wh >> 4, h = wh & 15;
    const float* W = ((which == 0) ? Wq : (which == 1) ? Wk : Wv) + (size_t)h * Dn * Kd;
    const int tid = threadIdx.x;
#pragma unroll
    for (int i = 0; i < 8; i++) {
        int idx = tid + 256 * i;
        int dr = idx >> 6, c = idx & 63;
        t[dr][c] = f2tf(W[(size_t)(d0 + dr) * 64 + c]);
    }
    __syncthreads();
#pragma unroll
    for (int i = 0; i < 8; i++) {
        int idx = tid + 256 * i;
        int row = idx >> 5, dd = idx & 31;
        g_wall[(size_t)((which << 10) + (h << 6) + row) * 1024 + d0 + dd] = t[dd][row];
    }
}

// ---------------------------------------------------------------------------
// GEMM mainloop (R5, known good): 128x128 tile, 256 threads = 8 warps
// (4m x 2n), warp 32x64.  2-stage cp.async, ldmatrix, XOR swizzle.
// ---------------------------------------------------------------------------
#define CP_WAIT1g asm volatile("cp.async.wait_group 1;")
#define GEMM_MAIN(Aptr, Bptr, KTOT)                                              \
    const int tid = threadIdx.x;                                                 \
    const int w = tid >> 5, lane = tid & 31;                                     \
    const int g = lane >> 2, tig = lane & 3;                                     \
    const int wm = w >> 1, wn = w & 1;                                           \
    const int rl = lane & 7, sub = lane >> 3;                                    \
    const int shA = sub >> 1, shB = sub & 1;                                     \
    extern __shared__ unsigned sm[];                                             \
    const unsigned sA = cvta_s(sm);                                              \
    const unsigned sB = sA + 2 * 4096 * 4;                                       \
    const int r0f = tid >> 3, cf = tid & 7;                                      \
    const unsigned dA0 = sA + ((r0f * 32 + ((cf ^ (r0f & 7)) << 2)) << 2);       \
    const unsigned dB0 = sB + ((r0f * 32 + ((cf ^ (r0f & 7)) << 2)) << 2);       \
    int rowA0 = wm * 32 + ((sub & 1) << 3) + rl;                                 \
    int wA0 = rowA0 * 32, xA0 = rowA0 & 7;                                       \
    int wA1 = (rowA0 + 16) * 32, xA1 = (rowA0 + 16) & 7;                         \
    int rowB0 = wn * 64 + ((sub >> 1) << 3) + rl;                                \
    int wB[4], xB[4];                                                            \
    _Pragma("unroll") for (int nj = 0; nj < 4; nj++) {                           \
        int rb = rowB0 + nj * 16; wB[nj] = rb * 32; xB[nj] = rb & 7; }           \
    float acc[2][8][4];                                                          \
    _Pragma("unroll") for (int mi = 0; mi < 2; mi++)                             \
    _Pragma("unroll") for (int ni = 0; ni < 8; ni++)                             \
    _Pragma("unroll") for (int q = 0; q < 4; q++) acc[mi][ni][q] = 0.f;          \
    _Pragma("unroll") for (int i = 0; i < 4; i++) {                              \
        cpa16(dA0 + i * 4096, Aptr + (size_t)(r0f + 32 * i) * 1024 + cf * 4);    \
        cpa16(dB0 + i * 4096, Bptr + (size_t)(r0f + 32 * i) * 1024 + cf * 4); }  \
    CP_COMMIT;                                                                   \
    const int NIT = (KTOT) / 32;                                                 \
    for (int it = 0; it < NIT; it++) {                                           \
        CP_WAIT0; __syncthreads();                                               \
        int buf = it & 1;                                                        \
        if (it + 1 < NIT) {                                                      \
            int kk = (it + 1) * 32;                                              \
            unsigned off = (buf ^ 1) * 16384;                                    \
            _Pragma("unroll") for (int i = 0; i < 4; i++) {                      \
                cpa16(dA0 + off + i * 4096,                                      \
                      Aptr + (size_t)(r0f + 32 * i) * 1024 + kk + cf * 4);       \
                cpa16(dB0 + off + i * 4096,                                      \
                      Bptr + (size_t)(r0f + 32 * i) * 1024 + kk + cf * 4); }     \
            CP_COMMIT;                                                           \
        }                                                                        \
        unsigned stoff = buf * 16384;                                            \
        _Pragma("unroll") for (int ks = 0; ks < 4; ks++) {                       \
            unsigned a0[4], a1[4], bq[4][4];                                     \
            ldsm4(a0, sA + stoff + ((wA0 + (((2 * ks + shA) ^ xA0) << 2)) << 2));\
            ldsm4(a1, sA + stoff + ((wA1 + (((2 * ks + shA) ^ xA1) << 2)) << 2));\
            _Pragma("unroll") for (int nj = 0; nj < 4; nj++)                     \
                ldsm4(bq[nj], sB + stoff +                                       \
                      ((wB[nj] + (((2 * ks + shB) ^ xB[nj]) << 2)) << 2));       \
            _Pragma("unroll") for (int ni = 0; ni < 8; ni++) {                   \
                unsigned b0 = bq[ni >> 1][(ni & 1) * 2];                         \
                unsigned b1 = bq[ni >> 1][(ni & 1) * 2 + 1];                     \
                mma8(acc[0][ni], a0, b0, b1);                                    \
                mma8(acc[1][ni], a1, b0, b1);                                    \
            }                                                                    \
        }                                                                        \
    }

#define GEMM_SMEM (2 * 4096 * 4 * 2)   // 64 KB

// ---------------------------------------------------------------------------
// Kernel 1: fused QKV GEMM; q pre-scaled by QSC (1/sqrt(K) * log2e)
// ---------------------------------------------------------------------------
__global__ __launch_bounds__(256, 2) void qkv_mma()
{
    const int mblk = blockIdx.x;
    const int nblk = blockIdx.y;
    const unsigned* Ag = g_xt + (size_t)mblk * 128 * Dn;
    const unsigned* Bg = g_wall + (size_t)nblk * 128 * 1024;

    GEMM_MAIN(Ag, Bg, 1024)

    const int which = nblk >> 3;
#pragma unroll
    for (int mi = 0; mi < 2; mi++) {
        int m = mblk * 128 + wm * 32 + mi * 16 + g;
        int b = m >> 11, t = m & 2047;
#pragma unroll
        for (int ni = 0; ni < 8; ni++) {
            int nl = nblk * 128 + wn * 64 + ni * 8 + 2 * tig;
            int hh = (nl >> 6) & 15, kcol = nl & 63;
            float c0 = acc[mi][ni][0], c1 = acc[mi][ni][1];
            float c2 = acc[mi][ni][2], c3 = acc[mi][ni][3];
            if (which == 0) {
                unsigned* p = g_q + ((size_t)(b * 16 + hh) * Tn + t) * 64 + kcol;
                *(uint2*)p = make_uint2(f2tf(c0 * QSC), f2tf(c1 * QSC));
                *(uint2*)(p + 8 * 64) = make_uint2(f2tf(c2 * QSC), f2tf(c3 * QSC));
            } else if (which == 1) {
                unsigned* p = g_k + ((size_t)(b * 16 + hh) * Tn + t) * 64 + kcol;
                *(uint2*)p = make_uint2(f2tf(c0), f2tf(c1));
                *(uint2*)(p + 8 * 64) = make_uint2(f2tf(c2), f2tf(c3));
            } else {
                unsigned* p = g_vt + ((size_t)(b * 16 + hh) * 64 + kcol) * Tn + t;
                p[0] = f2tf(c0); p[Tn] = f2tf(c1);
                p[8] = f2tf(c2); p[Tn + 8] = f2tf(c3);
            }
        }
    }
}

// ---------------------------------------------------------------------------
// Kernel 3: output projection
// ---------------------------------------------------------------------------
__global__ __launch_bounds__(256, 2) void proj_mma(const float* __restrict__ bo,
                                                   float* __restrict__ Y)
{
    const int mblk = blockIdx.x;
    const int nblk = blockIdx.y;
    const unsigned* Ag = g_ao + (size_t)mblk * 128 * HK;
    const unsigned* Bg = g_wot + (size_t)nblk * 128 * 1024;

    GEMM_MAIN(Ag, Bg, 1024)

#pragma unroll
    for (int mi = 0; mi < 2; mi++) {
        int m = mblk * 128 + wm * 32 + mi * 16 + g;
#pragma unroll
        for (int ni = 0; ni < 8; ni++) {
            int n = nblk * 128 + wn * 64 + ni * 8 + 2 * tig;
            float2 bb = *(const float2*)(bo + n);
            *(float2*)(Y + (size_t)m * HK + n) =
                make_float2(acc[mi][ni][0] + bb.x, acc[mi][ni][1] + bb.y);
            *(float2*)(Y + (size_t)(m + 8) * HK + n) =
                make_float2(acc[mi][ni][2] + bb.x, acc[mi][ni][3] + bb.y);
        }
    }
}

// ---------------------------------------------------------------------------
// Kernel 2: causal flash attention. 128 threads = 4 warps, warp owns 32 rows.
// NEW: softmax exp/store interleaved with PV mma at 2-block granularity so
// MUFU work hides under the tensor pipe instead of serializing.
// ---------------------------------------------------------------------------
__global__ __launch_bounds__(128, 2) void attn_kernel()
{
    extern __shared__ unsigned sm[];
    const unsigned sQ = cvta_s(sm);
    const unsigned sK = sQ + 8192 * 4;
    const unsigned sV = sK + 2 * 4096 * 4;

    const int qb = (int)gridDim.x - 1 - (int)blockIdx.x;  // big tiles first
    const int bh = blockIdx.y;
    const int b = bh >> 4, h = bh & 15;

    const int tid = threadIdx.x;
    const int w = tid >> 5, lane = tid & 31;
    const int g = lane >> 2, tig = lane & 3;
    const int rl = lane & 7, sub = lane >> 3;
    const int shq = sub >> 1, shb = sub & 1;

    const unsigned* Qg = g_q + ((size_t)bh * Tn + (size_t)qb * 128) * 64;
    const unsigned* Kg = g_k + (size_t)bh * Tn * 64;
    const unsigned* Vt = g_vt + (size_t)bh * 64 * Tn;

    const int frow = tid >> 4, fc = tid & 15;
    const unsigned foff = ((frow * 64 + ((fc >> 3) << 5) +
                            (((fc & 7) ^ (frow & 7)) << 2)) << 2);

#pragma unroll
    for (int i = 0; i < 16; i++)
        cpa16(sQ + foff + i * 2048, Qg + (size_t)(frow + 8 * i) * 64 + fc * 4);
#pragma unroll
    for (int i = 0; i < 8; i++) {
        cpa16(sK + foff + i * 2048, Kg + (size_t)(frow + 8 * i) * 64 + fc * 4);
        cpa16(sV + foff + i * 2048, Vt + (size_t)(frow + 8 * i) * Tn + fc * 4);
    }
    CP_COMMIT;
    CP_WAIT0;
    __syncthreads();

    unsigned qf[8][2][4];
    int wqm[2], xqm[2];
#pragma unroll
    for (int mi = 0; mi < 2; mi++) {
        int rowQ = w * 32 + mi * 16 + ((sub & 1) << 3) + rl;
        wqm[mi] = rowQ * 64; xqm[mi] = rowQ & 7;
#pragma unroll
        for (int ks = 0; ks < 8; ks++)
            ldsm4(qf[ks][mi], sQ + ((wqm[mi] + ((ks & 4) << 3) +
                  ((((2 * ks) & 7) + shq ^ xqm[mi]) << 2)) << 2));
    }

    int rowB0 = ((sub >> 1) << 3) + rl;
    int wKB[4], xKB[4];
#pragma unroll
    for (int nj = 0; nj < 4; nj++) {
        int rb = rowB0 + nj * 16; wKB[nj] = rb * 64; xKB[nj] = rb & 7;
    }

    float mrow[4], lrow[4];
    float o[2][8][4];
#pragma unroll
    for (int q = 0; q < 4; q++) { mrow[q] = -1e30f; lrow[q] = 0.f; }
#pragma unroll
    for (int mi = 0; mi < 2; mi++)
#pragma unroll
        for (int ni = 0; ni < 8; ni++)
#pragma unroll
            for (int q = 0; q < 4; q++) o[mi][ni][q] = 0.f;

    const int kbmax = 2 * qb + 1;

    for (int kb = 0; kb <= kbmax; kb++) {
        const int buf = kb & 1;
        if (kb) { CP_WAIT0; __syncthreads(); }
        if (kb < kbmax) {
            unsigned off = (buf ^ 1) * 16384;
            int s0g = (kb + 1) * 64;
#pragma unroll
            for (int i = 0; i < 8; i++) {
                cpa16(sK + off + foff + i * 2048,
                      Kg + (size_t)(s0g + frow + 8 * i) * 64 + fc * 4);
                cpa16(sV + off + foff + i * 2048,
                      Vt + (size_t)(frow + 8 * i) * Tn + s0g + fc * 4);
            }
            CP_COMMIT;
        }
        const unsigned stK = sK + buf * 16384;
        const unsigned stV = sV + buf * 16384;

        // S = Q @ K^T
        float s[2][8][4];
#pragma unroll
        for (int mi = 0; mi < 2; mi++)
#pragma unroll
            for (int ni = 0; ni < 8; ni++)
#pragma unroll
                for (int q = 0; q < 4; q++) s[mi][ni][q] = 0.f;
#pragma unroll
        for (int ks = 0; ks < 8; ks++) {
            unsigned bq[4][4];
#pragma unroll
            for (int nj = 0; nj < 4; nj++)
                ldsm4(bq[nj], stK + ((wKB[nj] + ((ks & 4) << 3) +
                      ((((2 * ks) & 7) + shb ^ xKB[nj]) << 2)) << 2));
#pragma unroll
            for (int ni = 0; ni < 8; ni++) {
                unsigned b0 = bq[ni >> 1][(ni & 1) * 2];
                unsigned b1 = bq[ni >> 1][(ni & 1) * 2 + 1];
                mma8(s[0][ni], qf[ks][0], b0, b1);
                mma8(s[1][ni], qf[ks][1], b0, b1);
            }
        }

        // causal mask (diagonal-touching tiles only)
        if (kb >= 2 * qb) {
#pragma unroll
            for (int mi = 0; mi < 2; mi++) {
                int grow0 = qb * 128 + w * 32 + mi * 16 + g;
#pragma unroll
                for (int ni = 0; ni < 8; ni++) {
                    int col = kb * 64 + ni * 8 + 2 * tig;
                    if (col > grow0)         s[mi][ni][0] = -1e30f;
                    if (col + 1 > grow0)     s[mi][ni][1] = -1e30f;
                    if (col > grow0 + 8)     s[mi][ni][2] = -1e30f;
                    if (col + 1 > grow0 + 8) s[mi][ni][3] = -1e30f;
                }
            }
        }

        // Phase 1: row max, rescale running state (base-2 domain)
#pragma unroll
        for (int mi = 0; mi < 2; mi++) {
            float x0 = -1e30f, x1 = -1e30f;
#pragma unroll
            for (int ni = 0; ni < 8; ni++) {
                x0 = fmaxf(x0, fmaxf(s[mi][ni][0], s[mi][ni][1]));
                x1 = fmaxf(x1, fmaxf(s[mi][ni][2], s[mi][ni][3]));
            }
#pragma unroll
            for (int off = 1; off < 4; off <<= 1) {
                x0 = fmaxf(x0, __shfl_xor_sync(0xffffffffu, x0, off));
                x1 = fmaxf(x1, __shfl_xor_sync(0xffffffffu, x1, off));
            }
            float mn0 = fmaxf(mrow[mi * 2], x0), mn1 = fmaxf(mrow[mi * 2 + 1], x1);
            float corr0 = exp2f(mrow[mi * 2] - mn0), corr1 = exp2f(mrow[mi * 2 + 1] - mn1);
            mrow[mi * 2] = mn0; mrow[mi * 2 + 1] = mn1;
            lrow[mi * 2] *= corr0; lrow[mi * 2 + 1] *= corr1;
#pragma unroll
            for (int ni = 0; ni < 8; ni++) {
                o[mi][ni][0] *= corr0; o[mi][ni][1] *= corr0;
                o[mi][ni][2] *= corr1; o[mi][ni][3] *= corr1;
            }
        }

        // Phase 2: interleaved exp/store + PV mma (2 column-blocks at a time)
        float rs[4] = {0.f, 0.f, 0.f, 0.f};
#pragma unroll
        for (int sb = 0; sb < 8; sb += 2) {
#pragma unroll
            for (int ni = sb; ni < sb + 2; ni++) {
#pragma unroll
                for (int mi = 0; mi < 2; mi++) {
                    unsigned t0 = f2tf(exp2f(s[mi][ni][0] - mrow[mi * 2]));
                    unsigned t1 = f2tf(exp2f(s[mi][ni][1] - mrow[mi * 2]));
                    unsigned t2 = f2tf(exp2f(s[mi][ni][2] - mrow[mi * 2 + 1]));
                    unsigned t3 = f2tf(exp2f(s[mi][ni][3] - mrow[mi * 2 + 1]));
                    rs[mi * 2]     += __uint_as_float(t0) + __uint_as_float(t1);
                    rs[mi * 2 + 1] += __uint_as_float(t2) + __uint_as_float(t3);
                    int rr0 = w * 32 + mi * 16 + g;
                    int rr1 = rr0 + 8;
                    int col = ni * 8 + 2 * tig;
                    unsigned w0 = (rr0 * 64 + (col & 32) +
                                   ((((col >> 2) & 7) ^ (rr0 & 7)) << 2) + (col & 3)) << 2;
                    unsigned w1 = (rr1 * 64 + (col & 32) +
                                   ((((col >> 2) & 7) ^ (rr1 & 7)) << 2) + (col & 3)) << 2;
                    *(uint2*)((char*)sm + w0) = make_uint2(t0, t1);
                    *(uint2*)((char*)sm + w1) = make_uint2(t2, t3);
                }
            }
            __syncwarp();
#pragma unroll
            for (int ss = sb; ss < sb + 2; ss++) {
                unsigned pa[2][4];
#pragma unroll
                for (int mi = 0; mi < 2; mi++)
                    ldsm4(pa[mi], sQ + ((wqm[mi] + ((ss & 4) << 3) +
                          ((((2 * ss) & 7) + shq ^ xqm[mi]) << 2)) << 2));
                unsigned bq[4][4];
#pragma unroll
                for (int nj = 0; nj < 4; nj++)
                    ldsm4(bq[nj], stV + ((wKB[nj] + ((ss & 4) << 3) +
                          ((((2 * ss) & 7) + shb ^ xKB[nj]) << 2)) << 2));
#pragma unroll
                for (int ni = 0; ni < 8; ni++) {
                    unsigned b0 = bq[ni >> 1][(ni & 1) * 2];
                    unsigned b1 = bq[ni >> 1][(ni & 1) * 2 + 1];
                    mma8(o[0][ni], pa[0], b0, b1);
                    mma8(o[1][ni], pa[1], b0, b1);
                }
            }
        }

        // fold partial sums into l
#pragma unroll
        for (int q = 0; q < 4; q++) {
            float r = rs[q];
#pragma unroll
            for (int off = 1; off < 4; off <<= 1)
                r += __shfl_xor_sync(0xffffffffu, r, off);
            lrow[q] += r;
        }
        __syncwarp();
    }

    // epilogue: normalize, write tf32 into g_ao head-concat layout
#pragma unroll
    for (int mi = 0; mi < 2; mi++) {
        float inv0 = 1.0f / lrow[mi * 2], inv1 = 1.0f / lrow[mi * 2 + 1];
        int rr = qb * 128 + w * 32 + mi * 16 + g;
        unsigned* Og = g_ao + ((size_t)b * Tn + rr) * HK + (size_t)h * Kd;
#pragma unroll
        for (int ni = 0; ni < 8; ni++) {
            int col = ni * 8 + 2 * tig;
            *(uint2*)(Og + col) =
                make_uint2(f2tf(o[mi][ni][0] * inv0), f2tf(o[mi][ni][1] * inv0));
            *(uint2*)(Og + 8 * HK + col) =
                make_uint2(f2tf(o[mi][ni][2] * inv1), f2tf(o[mi][ni][3] * inv1));
        }
    }
}

// ---------------------------------------------------------------------------
extern "C" void kernel_launch(void* const* d_in, const int* in_sizes, int n_in,
                              void* d_out, int out_size)
{
    (void)in_sizes; (void)n_in; (void)out_size;
    const float* X  = (const float*)d_in[0];
    const float* Wq = (const float*)d_in[1];
    const float* Wk = (const float*)d_in[2];
    const float* Wv = (const float*)d_in[3];
    const float* Wo = (const float*)d_in[4];
    const float* bo = (const float*)d_in[5];
    float* Y = (float*)d_out;

    const int attn_smem = (8192 + 2 * 4096 + 2 * 4096) * 4;  // 96 KB
    cudaFuncSetAttribute(attn_kernel, cudaFuncAttributeMaxDynamicSharedMemorySize, attn_smem);
    cudaFuncSetAttribute(qkv_mma,  cudaFuncAttributeMaxDynamicSharedMemorySize, GEMM_SMEM);
    cudaFuncSetAttribute(proj_mma, cudaFuncAttributeMaxDynamicSharedMemorySize, GEMM_SMEM);

    conv_kernel<<<8192, 256>>>((const float4*)X, (const float4*)Wo);
    gather_w<<<dim3(32, 48), 256>>>(Wq, Wk, Wv);
    qkv_mma<<<dim3(64, 24), 256, GEMM_SMEM>>>();
    attn_kernel<<<dim3(Tn / 128, Bn * Hn), 128, attn_smem>>>();
    proj_mma<<<dim3(64, 8), 256, GEMM_SMEM>>>(bo, Y);
}